// round 3
// baseline (speedup 1.0000x reference)
#include <cuda_runtime.h>
#include <cuda.h>
#include <cuda_bf16.h>
#include <cstdint>

#define BB      16384
#define IN_DIM  512
#define HH      512
#define KK      1024
#define NN      2048
#define TM      128
#define TN      128
#define TK      64
#define KCHUNKS 16
#define NSTAGE  3
#define CSZ     ((size_t)BB * HH)

#define SM_FULL0   0        // 3 mbarriers, 8B each
#define SM_STAGE0  1024
#define A_HI_OFF   0
#define A_LO_OFF   16384
#define B_HI_OFF   32768
#define B_LO_OFF   49152
#define STAGE_BYTES 65536
#define SMEM_TOTAL (1024 + NSTAGE * STAGE_BYTES)
#define CHUNK_TX   65536u

__device__ __align__(1024) __nv_bfloat16 g_Ahi[(size_t)BB * KK];
__device__ __align__(1024) __nv_bfloat16 g_Alo[(size_t)BB * KK];
__device__ __align__(1024) __nv_bfloat16 g_Bhi[(size_t)NN * KK];
__device__ __align__(1024) __nv_bfloat16 g_Blo[(size_t)NN * KK];
__device__ float g_bias[NN];   // indexed [4*h + gate]

__device__ __forceinline__ uint32_t smem_u32(const void* p) {
    return (uint32_t)__cvta_generic_to_shared(p);
}
__device__ __forceinline__ void mbar_init(uint32_t a, uint32_t cnt) {
    asm volatile("mbarrier.init.shared.b64 [%0], %1;" :: "r"(a), "r"(cnt) : "memory");
}
__device__ __forceinline__ void mbar_expect_tx(uint32_t a, uint32_t bytes) {
    asm volatile("mbarrier.arrive.expect_tx.shared.b64 _, [%0], %1;" :: "r"(a), "r"(bytes) : "memory");
}
__device__ __forceinline__ void mbar_wait(uint32_t a, uint32_t parity) {
    asm volatile(
        "{\n\t.reg .pred P1;\n\t"
        "LW_%=:\n\t"
        "mbarrier.try_wait.parity.acquire.cta.shared::cta.b64 P1, [%0], %1, 0x989680;\n\t"
        "@P1 bra.uni LD_%=;\n\t"
        "bra.uni LW_%=;\n\t"
        "LD_%=:\n\t}"
        :: "r"(a), "r"(parity) : "memory");
}
__device__ __forceinline__ void tma_load3d(uint32_t dst, const CUtensorMap* map,
                                           int cx_, int cy_, uint32_t mbar) {
    asm volatile(
        "cp.async.bulk.tensor.3d.shared::cta.global.tile.mbarrier::complete_tx::bytes "
        "[%0], [%1, {%2, %3, %4}], [%5];"
        :: "r"(dst), "l"(map), "r"(cx_), "r"(cy_), "r"(0), "r"(mbar) : "memory");
}
__device__ __forceinline__ void ldsm4(uint32_t* r, uint32_t addr) {
    asm volatile("ldmatrix.sync.aligned.m8n8.x4.shared.b16 {%0,%1,%2,%3}, [%4];"
        : "=r"(r[0]), "=r"(r[1]), "=r"(r[2]), "=r"(r[3]) : "r"(addr));
}
__device__ __forceinline__ void mma_bf16(float* d, const uint32_t* a, uint32_t b0, uint32_t b1) {
    asm volatile("mma.sync.aligned.m16n8k16.row.col.f32.bf16.bf16.f32 "
        "{%0,%1,%2,%3}, {%4,%5,%6,%7}, {%8,%9}, {%0,%1,%2,%3};"
        : "+f"(d[0]), "+f"(d[1]), "+f"(d[2]), "+f"(d[3])
        : "r"(a[0]), "r"(a[1]), "r"(a[2]), "r"(a[3]), "r"(b0), "r"(b1));
}
__device__ __forceinline__ float sigf(float x) { return 1.0f / (1.0f + __expf(-x)); }
__device__ __forceinline__ float tanh_f(float x) {
    float e = __expf(2.0f * x);
    return 1.0f - 2.0f / (e + 1.0f);
}

__device__ __forceinline__ void split_store(__nv_bfloat16* hi, __nv_bfloat16* lo, float4 v) {
    float f[4] = {v.x, v.y, v.z, v.w};
    uint32_t ph[2], pl[2];
    #pragma unroll
    for (int p = 0; p < 2; p++) {
        __nv_bfloat16 h0 = __float2bfloat16(f[2*p]);
        __nv_bfloat16 h1 = __float2bfloat16(f[2*p+1]);
        float l0 = f[2*p]   - __bfloat162float(h0);
        float l1 = f[2*p+1] - __bfloat162float(h1);
        ph[p] = (uint32_t)__bfloat16_as_ushort(h0) | ((uint32_t)__bfloat16_as_ushort(h1) << 16);
        __nv_bfloat16 g0 = __float2bfloat16(l0);
        __nv_bfloat16 g1 = __float2bfloat16(l1);
        pl[p] = (uint32_t)__bfloat16_as_ushort(g0) | ((uint32_t)__bfloat16_as_ushort(g1) << 16);
    }
    ((uint32_t*)hi)[0] = ph[0]; ((uint32_t*)hi)[1] = ph[1];
    ((uint32_t*)lo)[0] = pl[0]; ((uint32_t*)lo)[1] = pl[1];
}

// A = [x | hx] fused along K, hi/lo split
__global__ void prep_act(const float4* __restrict__ x4, const float4* __restrict__ hx4) {
    int t = blockIdx.x * blockDim.x + threadIdx.x;
    if (t >= BB * IN_DIM / 4) return;
    int m = t >> 7, k4 = (t & 127) << 2;
    size_t o = (size_t)m * KK + k4;
    split_store(&g_Ahi[o], &g_Alo[o], x4[t]);
    split_store(&g_Ahi[o + 512], &g_Alo[o + 512], hx4[t]);
}

// W columns permuted so each epilogue thread owns all 4 gates of its h values.
// n (0..2047): cta=n>>7, w=(n>>6)&1, rem=n&63, j=rem>>3, lp=rem&7, c=lp>>1, e=lp&1
// gate = 2*(j>>2)+e ; h = 32*cta + 16*w + 4*(j&3) + c ; src row = gate*512 + h
__global__ void prep_w(const float* __restrict__ Wx, const float* __restrict__ bx,
                       const float* __restrict__ Wh, const float* __restrict__ bh) {
    int t = blockIdx.x * blockDim.x + threadIdx.x;
    if (t >= NN * KK / 4) return;
    int n = t >> 8, k4 = (t & 255) << 2;
    int cta = n >> 7, w = (n >> 6) & 1, rem = n & 63;
    int j = rem >> 3, lp = rem & 7, c = lp >> 1, e = lp & 1;
    int gate = ((j >> 2) << 1) | e;
    int h = cta * 32 + w * 16 + 4 * (j & 3) + c;
    int src = gate * 512 + h;
    float4 v = (k4 < 512) ? ((const float4*)Wx)[(src * 512 + k4) >> 2]
                          : ((const float4*)Wh)[(src * 512 + k4 - 512) >> 2];
    size_t o = (size_t)n * KK + k4;
    split_store(&g_Bhi[o], &g_Blo[o], v);
    if (k4 == 0) g_bias[4 * h + gate] = bx[src] + bh[src];
}

__global__ void __launch_bounds__(256, 1) lstm_fused(
    const __grid_constant__ CUtensorMap tmAhi,
    const __grid_constant__ CUtensorMap tmAlo,
    const __grid_constant__ CUtensorMap tmBhi,
    const __grid_constant__ CUtensorMap tmBlo,
    const float* __restrict__ cx,
    const float* __restrict__ w_ci,
    const float* __restrict__ w_cf,
    const float* __restrict__ w_co,
    float* __restrict__ out)
{
    extern __shared__ __align__(1024) char smem[];
    uint32_t sb = smem_u32(smem);
    int tid = threadIdx.x, wid = tid >> 5, lane = tid & 31;
    int warp_m = wid & 3, warp_n = wid >> 2;           // 4x2 warp grid
    int tileN = blockIdx.x, tileM = blockIdx.y;

    if (tid == 0) {
        mbar_init(sb + SM_FULL0 + 0, 1);
        mbar_init(sb + SM_FULL0 + 8, 1);
        mbar_init(sb + SM_FULL0 + 16, 1);
        asm volatile("fence.proxy.async.shared::cta;" ::: "memory");
    }
    __syncthreads();

    if (tid == 0) {
        int mrow = tileM * TM, nrow = tileN * TN;
        #pragma unroll
        for (int s = 0; s < NSTAGE; s++) {
            uint32_t st = sb + SM_STAGE0 + s * STAGE_BYTES;
            uint32_t fb = sb + SM_FULL0 + 8 * s;
            mbar_expect_tx(fb, CHUNK_TX);
            tma_load3d(st + A_HI_OFF, &tmAhi, s * TK, mrow, fb);
            tma_load3d(st + A_LO_OFF, &tmAlo, s * TK, mrow, fb);
            tma_load3d(st + B_HI_OFF, &tmBhi, s * TK, nrow, fb);
            tma_load3d(st + B_LO_OFF, &tmBlo, s * TK, nrow, fb);
        }
    }

    // per-lane ldmatrix addressing (SW128): row = (lane&15), col-group = (lane>>4)*8 elems
    uint32_t xb = (lane >> 4) << 4;            // 16B col-group offset
    uint32_t sw = (lane & 7) << 4;             // SW128 XOR for this row
    uint32_t rowoff_a = (uint32_t)(warp_m * 32 + (lane & 15)) * 128;
    uint32_t rowoff_b = (uint32_t)(warp_n * 64 + (lane & 15)) * 128;

    float acc[2][8][4] = {};

    for (int k = 0; k < KCHUNKS; k++) {
        int s = k % NSTAGE;
        uint32_t par = (uint32_t)((k / NSTAGE) & 1);
        mbar_wait(sb + SM_FULL0 + 8 * s, par);
        uint32_t stage = sb + SM_STAGE0 + s * STAGE_BYTES;
        uint32_t abase_h = stage + A_HI_OFF + rowoff_a;
        uint32_t abase_l = stage + A_LO_OFF + rowoff_a;
        uint32_t bbase_h = stage + B_HI_OFF + rowoff_b;
        uint32_t bbase_l = stage + B_LO_OFF + rowoff_b;

        #pragma unroll
        for (int kk = 0; kk < 4; kk++) {
            uint32_t colo = ((uint32_t)(kk << 5) | xb) ^ sw;
            uint32_t a_hi[2][4], a_lo[2][4], b_hi[4][4], b_lo[4][4];
            #pragma unroll
            for (int mi = 0; mi < 2; mi++) {
                ldsm4(a_hi[mi], abase_h + mi * (16 * 128) + colo);
                ldsm4(a_lo[mi], abase_l + mi * (16 * 128) + colo);
            }
            #pragma unroll
            for (int bt = 0; bt < 4; bt++) {
                ldsm4(b_hi[bt], bbase_h + bt * (16 * 128) + colo);
                ldsm4(b_lo[bt], bbase_l + bt * (16 * 128) + colo);
            }
            #pragma unroll
            for (int mi = 0; mi < 2; mi++) {
                #pragma unroll
                for (int bt = 0; bt < 4; bt++) {
                    // n8 block j=2t uses regs {0,2}; j=2t+1 uses {1,3}
                    mma_bf16(acc[mi][2*bt],   a_hi[mi], b_hi[bt][0], b_hi[bt][2]);
                    mma_bf16(acc[mi][2*bt],   a_hi[mi], b_lo[bt][0], b_lo[bt][2]);
                    mma_bf16(acc[mi][2*bt],   a_lo[mi], b_hi[bt][0], b_hi[bt][2]);
                    mma_bf16(acc[mi][2*bt+1], a_hi[mi], b_hi[bt][1], b_hi[bt][3]);
                    mma_bf16(acc[mi][2*bt+1], a_hi[mi], b_lo[bt][1], b_lo[bt][3]);
                    mma_bf16(acc[mi][2*bt+1], a_lo[mi], b_hi[bt][1], b_hi[bt][3]);
                }
            }
        }
        __syncthreads();
        if (tid == 0 && k + NSTAGE < KCHUNKS) {
            uint32_t st = sb + SM_STAGE0 + s * STAGE_BYTES;
            uint32_t fb = sb + SM_FULL0 + 8 * s;
            mbar_expect_tx(fb, CHUNK_TX);
            int kx = (k + NSTAGE) * TK;
            tma_load3d(st + A_HI_OFF, &tmAhi, kx, tileM * TM, fb);
            tma_load3d(st + A_LO_OFF, &tmAlo, kx, tileM * TM, fb);
            tma_load3d(st + B_HI_OFF, &tmBhi, kx, tileN * TN, fb);
            tma_load3d(st + B_LO_OFF, &tmBlo, kx, tileN * TN, fb);
        }
    }

    // ---- fused LSTM epilogue, all in registers ----
    int c = lane & 3;
    int hb = tileN * 32 + warp_n * 16 + c;           // h = hb + 4*jj
    float wci[4], wcf[4], wco[4];
    float4 bias[4];
    #pragma unroll
    for (int jj = 0; jj < 4; jj++) {
        int h = hb + 4 * jj;
        wci[jj] = w_ci[h]; wcf[jj] = w_cf[h]; wco[jj] = w_co[h];
        bias[jj] = *reinterpret_cast<const float4*>(&g_bias[4 * h]);
    }
    #pragma unroll
    for (int mi = 0; mi < 2; mi++) {
        #pragma unroll
        for (int half = 0; half < 2; half++) {
            int m = tileM * TM + warp_m * 32 + mi * 16 + half * 8 + (lane >> 2);
            const float* cxr = cx + (size_t)m * HH;
            float* hout = out + (size_t)m * HH;
            float* coutp = out + CSZ + (size_t)m * HH;
            #pragma unroll
            for (int jj = 0; jj < 4; jj++) {
                int h = hb + 4 * jj;
                float ip = acc[mi][jj][half*2+0]   + bias[jj].x;
                float fp = acc[mi][jj][half*2+1]   + bias[jj].y;
                float gp = acc[mi][jj+4][half*2+0] + bias[jj].z;
                float op = acc[mi][jj+4][half*2+1] + bias[jj].w;
                float c0 = cxr[h];
                float ig = sigf(ip + c0 * wci[jj]);
                float fg = sigf(fp + c0 * wcf[jj]);
                float gg = tanh_f(gp);
                float cn = fg * c0 + ig * gg;
                float og = sigf(op + cn * wco[jj]);
                hout[h] = og * tanh_f(cn);
                coutp[h] = cn;
            }
        }
    }
}

// ---------------- host ----------------
typedef CUresult (*tmap_fn)(CUtensorMap*, CUtensorMapDataType, cuuint32_t, void*,
                            const cuuint64_t*, const cuuint64_t*, const cuuint32_t*,
                            const cuuint32_t*, CUtensorMapInterleave, CUtensorMapSwizzle,
                            CUtensorMapL2promotion, CUtensorMapFloatOOBfill);

static void make_map(tmap_fn enc, CUtensorMap* m, void* ptr, uint64_t d0, uint64_t d1,
                     uint32_t b0, uint32_t b1) {
    cuuint64_t dims[3]    = {d0, d1, 1};
    cuuint64_t strides[2] = {d0 * 2, d0 * d1 * 2};
    cuuint32_t box[3]     = {b0, b1, 1};
    cuuint32_t es[3]      = {1, 1, 1};
    enc(m, CU_TENSOR_MAP_DATA_TYPE_BFLOAT16, 3, ptr, dims, strides, box, es,
        CU_TENSOR_MAP_INTERLEAVE_NONE, CU_TENSOR_MAP_SWIZZLE_128B,
        CU_TENSOR_MAP_L2_PROMOTION_L2_128B, CU_TENSOR_MAP_FLOAT_OOB_FILL_NONE);
}

extern "C" void kernel_launch(void* const* d_in, const int* in_sizes, int n_in,
                              void* d_out, int out_size) {
    const float* x    = (const float*)d_in[0];
    const float* hx   = (const float*)d_in[1];
    const float* cx   = (const float*)d_in[2];
    const float* Wx   = (const float*)d_in[3];
    const float* bx   = (const float*)d_in[4];
    const float* Wh   = (const float*)d_in[5];
    const float* bh   = (const float*)d_in[6];
    const float* w_ci = (const float*)d_in[7];
    const float* w_cf = (const float*)d_in[8];
    const float* w_co = (const float*)d_in[9];
    float* out = (float*)d_out;

    tmap_fn enc = nullptr;
    cudaDriverEntryPointQueryResult qr;
    cudaGetDriverEntryPoint("cuTensorMapEncodeTiled", (void**)&enc, cudaEnableDefault, &qr);

    void *pAhi, *pAlo, *pBhi, *pBlo;
    cudaGetSymbolAddress(&pAhi, g_Ahi);
    cudaGetSymbolAddress(&pAlo, g_Alo);
    cudaGetSymbolAddress(&pBhi, g_Bhi);
    cudaGetSymbolAddress(&pBlo, g_Blo);

    CUtensorMap mAhi, mAlo, mBhi, mBlo;
    make_map(enc, &mAhi, pAhi, KK, BB, TK, TM);
    make_map(enc, &mAlo, pAlo, KK, BB, TK, TM);
    make_map(enc, &mBhi, pBhi, KK, NN, TK, TN);
    make_map(enc, &mBlo, pBlo, KK, NN, TK, TN);

    cudaFuncSetAttribute(lstm_fused, cudaFuncAttributeMaxDynamicSharedMemorySize, SMEM_TOTAL);

    prep_act<<<(BB * IN_DIM / 4 + 255) / 256, 256>>>((const float4*)x, (const float4*)hx);
    prep_w<<<(NN * KK / 4 + 255) / 256, 256>>>(Wx, bx, Wh, bh);

    dim3 grid(NN / TN, BB / TM);
    lstm_fused<<<grid, 256, SMEM_TOTAL>>>(mAhi, mAlo, mBhi, mBlo,
                                          cx, w_ci, w_cf, w_co, out);
}

// round 4
// speedup vs baseline: 2.0719x; 2.0719x over previous
#include <cuda_runtime.h>
#include <cuda.h>
#include <cuda_bf16.h>
#include <cuda_fp16.h>
#include <cstdint>

#define BB      16384
#define IN_DIM  512
#define HH      512
#define KK      1024
#define NN      2048
#define TM      128
#define TN      256
#define TK      64
#define KCHUNKS 16
#define NSTAGE  4
#define CSZ     ((size_t)BB * HH)

#define SM_FULL0   0          // 4 mbarriers, 8B each
#define SM_STAGE0  1024
#define A_OFF      0          // 128x64 fp16 = 16KB
#define B_OFF      16384      // 256x64 fp16 = 32KB
#define STAGE_BYTES 49152
#define SMEM_TOTAL (1024 + NSTAGE * STAGE_BYTES)
#define CHUNK_TX   49152u

__device__ __align__(1024) __half g_Ah[(size_t)BB * KK];
__device__ __align__(1024) __half g_Bh[(size_t)NN * KK];
__device__ float g_bias[NN];   // indexed [4*h + gate]

__device__ __forceinline__ uint32_t smem_u32(const void* p) {
    return (uint32_t)__cvta_generic_to_shared(p);
}
__device__ __forceinline__ void mbar_init(uint32_t a, uint32_t cnt) {
    asm volatile("mbarrier.init.shared.b64 [%0], %1;" :: "r"(a), "r"(cnt) : "memory");
}
__device__ __forceinline__ void mbar_expect_tx(uint32_t a, uint32_t bytes) {
    asm volatile("mbarrier.arrive.expect_tx.shared.b64 _, [%0], %1;" :: "r"(a), "r"(bytes) : "memory");
}
__device__ __forceinline__ void mbar_wait(uint32_t a, uint32_t parity) {
    asm volatile(
        "{\n\t.reg .pred P1;\n\t"
        "LW_%=:\n\t"
        "mbarrier.try_wait.parity.acquire.cta.shared::cta.b64 P1, [%0], %1, 0x989680;\n\t"
        "@P1 bra.uni LD_%=;\n\t"
        "bra.uni LW_%=;\n\t"
        "LD_%=:\n\t}"
        :: "r"(a), "r"(parity) : "memory");
}
__device__ __forceinline__ void tma_load3d(uint32_t dst, const CUtensorMap* map,
                                           int cx_, int cy_, uint32_t mbar) {
    asm volatile(
        "cp.async.bulk.tensor.3d.shared::cta.global.tile.mbarrier::complete_tx::bytes "
        "[%0], [%1, {%2, %3, %4}], [%5];"
        :: "r"(dst), "l"(map), "r"(cx_), "r"(cy_), "r"(0), "r"(mbar) : "memory");
}
__device__ __forceinline__ void ldsm4(uint32_t* r, uint32_t addr) {
    asm volatile("ldmatrix.sync.aligned.m8n8.x4.shared.b16 {%0,%1,%2,%3}, [%4];"
        : "=r"(r[0]), "=r"(r[1]), "=r"(r[2]), "=r"(r[3]) : "r"(addr));
}
__device__ __forceinline__ void mma_f16(float* d, const uint32_t* a, uint32_t b0, uint32_t b1) {
    asm volatile("mma.sync.aligned.m16n8k16.row.col.f32.f16.f16.f32 "
        "{%0,%1,%2,%3}, {%4,%5,%6,%7}, {%8,%9}, {%0,%1,%2,%3};"
        : "+f"(d[0]), "+f"(d[1]), "+f"(d[2]), "+f"(d[3])
        : "r"(a[0]), "r"(a[1]), "r"(a[2]), "r"(a[3]), "r"(b0), "r"(b1));
}
__device__ __forceinline__ float sigf(float x) { return 1.0f / (1.0f + __expf(-x)); }
__device__ __forceinline__ float tanh_f(float x) {
    float e = __expf(2.0f * x);
    return 1.0f - 2.0f / (e + 1.0f);
}
__device__ __forceinline__ void h4_store(__half* dst, float4 v) {
    uint32_t p0 = (uint32_t)__half_as_ushort(__float2half_rn(v.x)) |
                  ((uint32_t)__half_as_ushort(__float2half_rn(v.y)) << 16);
    uint32_t p1 = (uint32_t)__half_as_ushort(__float2half_rn(v.z)) |
                  ((uint32_t)__half_as_ushort(__float2half_rn(v.w)) << 16);
    ((uint32_t*)dst)[0] = p0;
    ((uint32_t*)dst)[1] = p1;
}

// A = [x | hx] fused along K, fp16
__global__ void prep_act(const float4* __restrict__ x4, const float4* __restrict__ hx4) {
    int t = blockIdx.x * blockDim.x + threadIdx.x;
    if (t >= BB * IN_DIM / 4) return;
    int m = t >> 7, k4 = (t & 127) << 2;
    size_t o = (size_t)m * KK + k4;
    h4_store(&g_Ah[o], x4[t]);
    h4_store(&g_Ah[o + 512], hx4[t]);
}

// W columns permuted so each epilogue thread owns all 4 gates of its h values.
// n (0..2047): cta=n>>8, wn=(n>>7)&1, j=(n>>3)&15, p=n&7, c=p>>1, e=p&1
// gate = 2*(j>>3)+e ; h = 64*cta + 32*wn + 4*(j&7) + c ; src row = gate*512 + h
__global__ void prep_w(const float* __restrict__ Wx, const float* __restrict__ bx,
                       const float* __restrict__ Wh, const float* __restrict__ bh) {
    int t = blockIdx.x * blockDim.x + threadIdx.x;
    if (t >= NN * KK / 4) return;
    int n = t >> 8, k4 = (t & 255) << 2;
    int cta = n >> 8, wn = (n >> 7) & 1, j = (n >> 3) & 15, p = n & 7;
    int c = p >> 1, e = p & 1;
    int gate = ((j >> 3) << 1) | e;
    int h = cta * 64 + wn * 32 + 4 * (j & 7) + c;
    int src = gate * 512 + h;
    float4 v = (k4 < 512) ? ((const float4*)Wx)[(src * 512 + k4) >> 2]
                          : ((const float4*)Wh)[(src * 512 + k4 - 512) >> 2];
    h4_store(&g_Bh[(size_t)n * KK + k4], v);
    if (k4 == 0) g_bias[4 * h + gate] = bx[src] + bh[src];
}

__global__ void __launch_bounds__(256, 1) lstm_fused(
    const __grid_constant__ CUtensorMap tmA,
    const __grid_constant__ CUtensorMap tmB,
    const float* __restrict__ cx,
    const float* __restrict__ w_ci,
    const float* __restrict__ w_cf,
    const float* __restrict__ w_co,
    float* __restrict__ out)
{
    extern __shared__ __align__(1024) char smem[];
    uint32_t sb = smem_u32(smem);
    int tid = threadIdx.x, wid = tid >> 5, lane = tid & 31;
    int warp_m = wid & 3, warp_n = wid >> 2;           // 4x2 warp grid; warp tile 32x128
    int tileN = blockIdx.x, tileM = blockIdx.y;

    if (tid == 0) {
        #pragma unroll
        for (int s = 0; s < NSTAGE; s++) mbar_init(sb + SM_FULL0 + 8 * s, 1);
        asm volatile("fence.proxy.async.shared::cta;" ::: "memory");
    }
    __syncthreads();

    if (tid == 0) {
        int mrow = tileM * TM, nrow = tileN * TN;
        #pragma unroll
        for (int s = 0; s < NSTAGE - 1; s++) {
            uint32_t st = sb + SM_STAGE0 + s * STAGE_BYTES;
            uint32_t fb = sb + SM_FULL0 + 8 * s;
            mbar_expect_tx(fb, CHUNK_TX);
            tma_load3d(st + A_OFF, &tmA, s * TK, mrow, fb);
            tma_load3d(st + B_OFF, &tmB, s * TK, nrow, fb);
        }
    }

    // ldmatrix addressing (SW128): rows 128B apart
    uint32_t xb = (lane >> 4) << 4;
    uint32_t sw = (lane & 7) << 4;
    uint32_t rowoff_a = (uint32_t)(warp_m * 32 + (lane & 15)) * 128;
    uint32_t rowoff_b = (uint32_t)(warp_n * 128 + (lane & 15)) * 128;

    float acc[2][16][4] = {};

    for (int k = 0; k < KCHUNKS; k++) {
        int s = k % NSTAGE;
        uint32_t par = (uint32_t)((k / NSTAGE) & 1);
        // issue the stage that is (NSTAGE-1) ahead into the slot freed last iter
        if (tid == 0 && k + NSTAGE - 1 < KCHUNKS) {
            int kl = k + NSTAGE - 1;
            int sl = kl % NSTAGE;
            uint32_t st = sb + SM_STAGE0 + sl * STAGE_BYTES;
            uint32_t fb = sb + SM_FULL0 + 8 * sl;
            mbar_expect_tx(fb, CHUNK_TX);
            tma_load3d(st + A_OFF, &tmA, kl * TK, tileM * TM, fb);
            tma_load3d(st + B_OFF, &tmB, kl * TK, tileN * TN, fb);
        }
        mbar_wait(sb + SM_FULL0 + 8 * s, par);
        uint32_t stage = sb + SM_STAGE0 + s * STAGE_BYTES;
        uint32_t abase = stage + A_OFF + rowoff_a;
        uint32_t bbase = stage + B_OFF + rowoff_b;

        #pragma unroll
        for (int kk = 0; kk < 4; kk++) {
            uint32_t colo = ((uint32_t)(kk << 5) | xb) ^ sw;
            uint32_t a[2][4], b[8][4];
            #pragma unroll
            for (int mi = 0; mi < 2; mi++)
                ldsm4(a[mi], abase + mi * (16 * 128) + colo);
            #pragma unroll
            for (int bt = 0; bt < 8; bt++)
                ldsm4(b[bt], bbase + bt * (16 * 128) + colo);
            #pragma unroll
            for (int bt = 0; bt < 8; bt++) {
                #pragma unroll
                for (int mi = 0; mi < 2; mi++) {
                    mma_f16(acc[mi][2*bt],   a[mi], b[bt][0], b[bt][2]);
                    mma_f16(acc[mi][2*bt+1], a[mi], b[bt][1], b[bt][3]);
                }
            }
        }
        __syncthreads();   // stage s now free for reuse next iteration
    }

    // ---- fused LSTM epilogue, all in registers ----
    int c = lane & 3;
    int hb = tileN * 64 + warp_n * 32 + c;          // h = hb + 4*jj, jj=0..7
    float wci[8], wcf[8], wco[8];
    float4 bias[8];
    #pragma unroll
    for (int jj = 0; jj < 8; jj++) {
        int h = hb + 4 * jj;
        wci[jj] = w_ci[h]; wcf[jj] = w_cf[h]; wco[jj] = w_co[h];
        bias[jj] = *reinterpret_cast<const float4*>(&g_bias[4 * h]);
    }
    #pragma unroll
    for (int mi = 0; mi < 2; mi++) {
        #pragma unroll
        for (int half = 0; half < 2; half++) {
            int m = tileM * TM + warp_m * 32 + mi * 16 + half * 8 + (lane >> 2);
            const float* cxr = cx + (size_t)m * HH;
            float* hout = out + (size_t)m * HH;
            float* coutp = out + CSZ + (size_t)m * HH;
            #pragma unroll
            for (int jj = 0; jj < 8; jj++) {
                int h = hb + 4 * jj;
                float ip = acc[mi][jj][2*half+0]   + bias[jj].x;
                float fp = acc[mi][jj][2*half+1]   + bias[jj].y;
                float gp = acc[mi][jj+8][2*half+0] + bias[jj].z;
                float op = acc[mi][jj+8][2*half+1] + bias[jj].w;
                float c0 = cxr[h];
                float ig = sigf(ip + c0 * wci[jj]);
                float fg = sigf(fp + c0 * wcf[jj]);
                float gg = tanh_f(gp);
                float cn = fg * c0 + ig * gg;
                float og = sigf(op + cn * wco[jj]);
                hout[h] = og * tanh_f(cn);
                coutp[h] = cn;
            }
        }
    }
}

// ---------------- host ----------------
typedef CUresult (*tmap_fn)(CUtensorMap*, CUtensorMapDataType, cuuint32_t, void*,
                            const cuuint64_t*, const cuuint64_t*, const cuuint32_t*,
                            const cuuint32_t*, CUtensorMapInterleave, CUtensorMapSwizzle,
                            CUtensorMapL2promotion, CUtensorMapFloatOOBfill);

static void make_map(tmap_fn enc, CUtensorMap* m, void* ptr, uint64_t d0, uint64_t d1,
                     uint32_t b0, uint32_t b1) {
    cuuint64_t dims[3]    = {d0, d1, 1};
    cuuint64_t strides[2] = {d0 * 2, d0 * d1 * 2};
    cuuint32_t box[3]     = {b0, b1, 1};
    cuuint32_t es[3]      = {1, 1, 1};
    enc(m, CU_TENSOR_MAP_DATA_TYPE_FLOAT16, 3, ptr, dims, strides, box, es,
        CU_TENSOR_MAP_INTERLEAVE_NONE, CU_TENSOR_MAP_SWIZZLE_128B,
        CU_TENSOR_MAP_L2_PROMOTION_L2_128B, CU_TENSOR_MAP_FLOAT_OOB_FILL_NONE);
}

extern "C" void kernel_launch(void* const* d_in, const int* in_sizes, int n_in,
                              void* d_out, int out_size) {
    const float* x    = (const float*)d_in[0];
    const float* hx   = (const float*)d_in[1];
    const float* cx   = (const float*)d_in[2];
    const float* Wx   = (const float*)d_in[3];
    const float* bx   = (const float*)d_in[4];
    const float* Wh   = (const float*)d_in[5];
    const float* bh   = (const float*)d_in[6];
    const float* w_ci = (const float*)d_in[7];
    const float* w_cf = (const float*)d_in[8];
    const float* w_co = (const float*)d_in[9];
    float* out = (float*)d_out;

    tmap_fn enc = nullptr;
    cudaDriverEntryPointQueryResult qr;
    cudaGetDriverEntryPoint("cuTensorMapEncodeTiled", (void**)&enc, cudaEnableDefault, &qr);

    void *pA, *pB;
    cudaGetSymbolAddress(&pA, g_Ah);
    cudaGetSymbolAddress(&pB, g_Bh);

    CUtensorMap mA, mB;
    make_map(enc, &mA, pA, KK, BB, TK, TM);
    make_map(enc, &mB, pB, KK, NN, TK, TN);

    cudaFuncSetAttribute(lstm_fused, cudaFuncAttributeMaxDynamicSharedMemorySize, SMEM_TOTAL);

    prep_act<<<(BB * IN_DIM / 4 + 255) / 256, 256>>>((const float4*)x, (const float4*)hx);
    prep_w<<<(NN * KK / 4 + 255) / 256, 256>>>(Wx, bx, Wh, bh);

    dim3 grid(NN / TN, BB / TM);
    lstm_fused<<<grid, 256, SMEM_TOTAL>>>(mA, mB, cx, w_ci, w_cf, w_co, out);
}

// round 5
// speedup vs baseline: 2.4089x; 1.1626x over previous
#include <cuda_runtime.h>
#include <cuda.h>
#include <cuda_bf16.h>
#include <cuda_fp16.h>
#include <cstdint>

#define BB      16384
#define IN_DIM  512
#define HH      512
#define KK      1024
#define NN      2048
#define TM      128
#define TN      256
#define TK      64
#define KCHUNKS 16
#define NSTAGE  4
#define CSZ     ((size_t)BB * HH)

#define SM_FULL0   0          // 4 mbarriers
#define SM_STAGE0  1024
#define A_OFF      0          // 128x64 fp16 = 16KB
#define B_OFF      16384      // 256x64 fp16 = 32KB
#define STAGE_BYTES 49152
#define SMEM_TOTAL (1024 + NSTAGE * STAGE_BYTES)
#define CHUNK_TX   49152u

__device__ __align__(1024) __half g_Ah[(size_t)BB * KK];
__device__ __align__(1024) __half g_Bh[(size_t)NN * KK];
__device__ float g_bias[NN];   // [4*h + gate]

__device__ __forceinline__ uint32_t smem_u32(const void* p) {
    return (uint32_t)__cvta_generic_to_shared(p);
}
__device__ __forceinline__ void mbar_init(uint32_t a, uint32_t cnt) {
    asm volatile("mbarrier.init.shared.b64 [%0], %1;" :: "r"(a), "r"(cnt) : "memory");
}
__device__ __forceinline__ void mbar_expect_tx(uint32_t a, uint32_t bytes) {
    asm volatile("mbarrier.arrive.expect_tx.shared.b64 _, [%0], %1;" :: "r"(a), "r"(bytes) : "memory");
}
__device__ __forceinline__ void mbar_wait(uint32_t a, uint32_t parity) {
    asm volatile(
        "{\n\t.reg .pred P1;\n\t"
        "LW_%=:\n\t"
        "mbarrier.try_wait.parity.acquire.cta.shared::cta.b64 P1, [%0], %1, 0x989680;\n\t"
        "@P1 bra.uni LD_%=;\n\t"
        "bra.uni LW_%=;\n\t"
        "LD_%=:\n\t}"
        :: "r"(a), "r"(parity) : "memory");
}
__device__ __forceinline__ void tma_load3d(uint32_t dst, const CUtensorMap* map,
                                           int cx_, int cy_, uint32_t mbar) {
    asm volatile(
        "cp.async.bulk.tensor.3d.shared::cta.global.tile.mbarrier::complete_tx::bytes "
        "[%0], [%1, {%2, %3, %4}], [%5];"
        :: "r"(dst), "l"(map), "r"(cx_), "r"(cy_), "r"(0), "r"(mbar) : "memory");
}
__device__ __forceinline__ void ldsm4(uint32_t* r, uint32_t addr) {
    asm volatile("ldmatrix.sync.aligned.m8n8.x4.shared.b16 {%0,%1,%2,%3}, [%4];"
        : "=r"(r[0]), "=r"(r[1]), "=r"(r[2]), "=r"(r[3]) : "r"(addr));
}
__device__ __forceinline__ void mma_f16(float* d, const uint32_t* a, uint32_t b0, uint32_t b1) {
    asm volatile("mma.sync.aligned.m16n8k16.row.col.f32.f16.f16.f32 "
        "{%0,%1,%2,%3}, {%4,%5,%6,%7}, {%8,%9}, {%0,%1,%2,%3};"
        : "+f"(d[0]), "+f"(d[1]), "+f"(d[2]), "+f"(d[3])
        : "r"(a[0]), "r"(a[1]), "r"(a[2]), "r"(a[3]), "r"(b0), "r"(b1));
}
__device__ __forceinline__ float sigf(float x) { return 1.0f / (1.0f + __expf(-x)); }
__device__ __forceinline__ float tanh_f(float x) {
    float e = __expf(2.0f * x);
    return 1.0f - 2.0f / (e + 1.0f);
}
__device__ __forceinline__ void h4_store(__half* dst, float4 v) {
    uint32_t p0 = (uint32_t)__half_as_ushort(__float2half_rn(v.x)) |
                  ((uint32_t)__half_as_ushort(__float2half_rn(v.y)) << 16);
    uint32_t p1 = (uint32_t)__half_as_ushort(__float2half_rn(v.z)) |
                  ((uint32_t)__half_as_ushort(__float2half_rn(v.w)) << 16);
    ((uint32_t*)dst)[0] = p0;
    ((uint32_t*)dst)[1] = p1;
}

// A = [x | hx] fused along K, fp16
__global__ void prep_act(const float4* __restrict__ x4, const float4* __restrict__ hx4) {
    int t = blockIdx.x * blockDim.x + threadIdx.x;
    if (t >= BB * IN_DIM / 4) return;
    int m = t >> 7, k4 = (t & 127) << 2;
    size_t o = (size_t)m * KK + k4;
    h4_store(&g_Ah[o], x4[t]);
    h4_store(&g_Ah[o + 512], hx4[t]);
}

// W columns permuted for 4x4 warp grid, warp tile 32x64.
// n = 256*ctaN + 64*wn + 8*j + 2*c + e  (j:0..7, c:0..3, e:0..1)
// gate = 2*(j>>2) + e ; h = 64*ctaN + 16*wn + 4*(j&3) + c ; src = gate*512 + h
__global__ void prep_w(const float* __restrict__ Wx, const float* __restrict__ bx,
                       const float* __restrict__ Wh, const float* __restrict__ bh) {
    int t = blockIdx.x * blockDim.x + threadIdx.x;
    if (t >= NN * KK / 4) return;
    int n = t >> 8, k4 = (t & 255) << 2;
    int ctaN = n >> 8, wn = (n >> 6) & 3, loc = n & 63;
    int j = loc >> 3, p = loc & 7, c = p >> 1, e = p & 1;
    int gate = ((j >> 2) << 1) | e;
    int h = ctaN * 64 + wn * 16 + 4 * (j & 3) + c;
    int src = gate * 512 + h;
    float4 v = (k4 < 512) ? ((const float4*)Wx)[(src * 512 + k4) >> 2]
                          : ((const float4*)Wh)[(src * 512 + k4 - 512) >> 2];
    h4_store(&g_Bh[(size_t)n * KK + k4], v);
    if (k4 == 0) g_bias[4 * h + gate] = bx[src] + bh[src];
}

__global__ void __launch_bounds__(512, 1) lstm_fused(
    const __grid_constant__ CUtensorMap tmA,
    const __grid_constant__ CUtensorMap tmB,
    const float* __restrict__ cx,
    const float* __restrict__ w_ci,
    const float* __restrict__ w_cf,
    const float* __restrict__ w_co,
    float* __restrict__ out)
{
    extern __shared__ __align__(1024) char smem[];
    uint32_t sb = smem_u32(smem);
    int tid = threadIdx.x, wid = tid >> 5, lane = tid & 31;
    int warp_m = wid & 3, warp_n = wid >> 2;     // 4x4 warp grid; warp tile 32x64
    int tileN = blockIdx.x, tileM = blockIdx.y;

    if (tid == 0) {
        #pragma unroll
        for (int s = 0; s < NSTAGE; s++) mbar_init(sb + SM_FULL0 + 8 * s, 1);
        asm volatile("fence.proxy.async.shared::cta;" ::: "memory");
    }
    __syncthreads();

    if (tid == 0) {
        int mrow = tileM * TM, nrow = tileN * TN;
        #pragma unroll
        for (int s = 0; s < NSTAGE - 1; s++) {
            uint32_t st = sb + SM_STAGE0 + s * STAGE_BYTES;
            uint32_t fb = sb + SM_FULL0 + 8 * s;
            mbar_expect_tx(fb, CHUNK_TX);
            tma_load3d(st + A_OFF, &tmA, s * TK, mrow, fb);
            tma_load3d(st + B_OFF, &tmB, s * TK, nrow, fb);
        }
    }

    uint32_t xb = (lane >> 4) << 4;
    uint32_t sw = (lane & 7) << 4;
    uint32_t rowoff_a = (uint32_t)(warp_m * 32 + (lane & 15)) * 128;
    uint32_t rowoff_b = (uint32_t)(warp_n * 64 + (lane & 15)) * 128;

    float acc[2][8][4] = {};

    for (int k = 0; k < KCHUNKS; k++) {
        int s = k % NSTAGE;
        uint32_t par = (uint32_t)((k / NSTAGE) & 1);
        if (tid == 0 && k + NSTAGE - 1 < KCHUNKS) {
            int kl = k + NSTAGE - 1;
            int sl = kl % NSTAGE;
            uint32_t st = sb + SM_STAGE0 + sl * STAGE_BYTES;
            uint32_t fb = sb + SM_FULL0 + 8 * sl;
            mbar_expect_tx(fb, CHUNK_TX);
            tma_load3d(st + A_OFF, &tmA, kl * TK, tileM * TM, fb);
            tma_load3d(st + B_OFF, &tmB, kl * TK, tileN * TN, fb);
        }
        mbar_wait(sb + SM_FULL0 + 8 * s, par);
        uint32_t stage = sb + SM_STAGE0 + s * STAGE_BYTES;
        uint32_t abase = stage + A_OFF + rowoff_a;
        uint32_t bbase = stage + B_OFF + rowoff_b;

        #pragma unroll
        for (int kk = 0; kk < 4; kk++) {
            uint32_t colo = ((uint32_t)(kk << 5) | xb) ^ sw;
            uint32_t a[2][4], b[4][4];
            #pragma unroll
            for (int mi = 0; mi < 2; mi++)
                ldsm4(a[mi], abase + mi * (16 * 128) + colo);
            #pragma unroll
            for (int bt = 0; bt < 4; bt++)
                ldsm4(b[bt], bbase + bt * (16 * 128) + colo);
            #pragma unroll
            for (int bt = 0; bt < 4; bt++) {
                #pragma unroll
                for (int mi = 0; mi < 2; mi++) {
                    mma_f16(acc[mi][2*bt],   a[mi], b[bt][0], b[bt][2]);
                    mma_f16(acc[mi][2*bt+1], a[mi], b[bt][1], b[bt][3]);
                }
            }
        }
        __syncthreads();
    }

    // ---- fused LSTM epilogue, pure registers ----
    int c = lane & 3;
    int hb = tileN * 64 + warp_n * 16 + c;        // h = hb + 4*hsub, hsub=0..3
    float wci[4], wcf[4], wco[4];
    float4 bias[4];
    #pragma unroll
    for (int jj = 0; jj < 4; jj++) {
        int h = hb + 4 * jj;
        wci[jj] = w_ci[h]; wcf[jj] = w_cf[h]; wco[jj] = w_co[h];
        bias[jj] = *reinterpret_cast<const float4*>(&g_bias[4 * h]);
    }
    #pragma unroll
    for (int mi = 0; mi < 2; mi++) {
        #pragma unroll
        for (int half = 0; half < 2; half++) {
            int m = tileM * TM + warp_m * 32 + mi * 16 + half * 8 + (lane >> 2);
            const float* cxr = cx + (size_t)m * HH;
            float* hout = out + (size_t)m * HH;
            float* coutp = out + CSZ + (size_t)m * HH;
            #pragma unroll
            for (int jj = 0; jj < 4; jj++) {
                int h = hb + 4 * jj;
                float ip = acc[mi][jj][2*half+0]   + bias[jj].x;
                float fp = acc[mi][jj][2*half+1]   + bias[jj].y;
                float gp = acc[mi][jj+4][2*half+0] + bias[jj].z;
                float op = acc[mi][jj+4][2*half+1] + bias[jj].w;
                float c0 = cxr[h];
                float ig = sigf(ip + c0 * wci[jj]);
                float fg = sigf(fp + c0 * wcf[jj]);
                float gg = tanh_f(gp);
                float cn = fg * c0 + ig * gg;
                float og = sigf(op + cn * wco[jj]);
                hout[h] = og * tanh_f(cn);
                coutp[h] = cn;
            }
        }
    }
}

// ---------------- host ----------------
typedef CUresult (*tmap_fn)(CUtensorMap*, CUtensorMapDataType, cuuint32_t, void*,
                            const cuuint64_t*, const cuuint64_t*, const cuuint32_t*,
                            const cuuint32_t*, CUtensorMapInterleave, CUtensorMapSwizzle,
                            CUtensorMapL2promotion, CUtensorMapFloatOOBfill);

static void make_map(tmap_fn enc, CUtensorMap* m, void* ptr, uint64_t d0, uint64_t d1,
                     uint32_t b0, uint32_t b1) {
    cuuint64_t dims[3]    = {d0, d1, 1};
    cuuint64_t strides[2] = {d0 * 2, d0 * d1 * 2};
    cuuint32_t box[3]     = {b0, b1, 1};
    cuuint32_t es[3]      = {1, 1, 1};
    enc(m, CU_TENSOR_MAP_DATA_TYPE_FLOAT16, 3, ptr, dims, strides, box, es,
        CU_TENSOR_MAP_INTERLEAVE_NONE, CU_TENSOR_MAP_SWIZZLE_128B,
        CU_TENSOR_MAP_L2_PROMOTION_L2_128B, CU_TENSOR_MAP_FLOAT_OOB_FILL_NONE);
}

extern "C" void kernel_launch(void* const* d_in, const int* in_sizes, int n_in,
                              void* d_out, int out_size) {
    const float* x    = (const float*)d_in[0];
    const float* hx   = (const float*)d_in[1];
    const float* cx   = (const float*)d_in[2];
    const float* Wx   = (const float*)d_in[3];
    const float* bx   = (const float*)d_in[4];
    const float* Wh   = (const float*)d_in[5];
    const float* bh   = (const float*)d_in[6];
    const float* w_ci = (const float*)d_in[7];
    const float* w_cf = (const float*)d_in[8];
    const float* w_co = (const float*)d_in[9];
    float* out = (float*)d_out;

    tmap_fn enc = nullptr;
    cudaDriverEntryPointQueryResult qr;
    cudaGetDriverEntryPoint("cuTensorMapEncodeTiled", (void**)&enc, cudaEnableDefault, &qr);

    void *pA, *pB;
    cudaGetSymbolAddress(&pA, g_Ah);
    cudaGetSymbolAddress(&pB, g_Bh);

    CUtensorMap mA, mB;
    make_map(enc, &mA, pA, KK, BB, TK, TM);
    make_map(enc, &mB, pB, KK, NN, TK, TN);

    cudaFuncSetAttribute(lstm_fused, cudaFuncAttributeMaxDynamicSharedMemorySize, SMEM_TOTAL);

    prep_act<<<(BB * IN_DIM / 4 + 255) / 256, 256>>>((const float4*)x, (const float4*)hx);
    prep_w<<<(NN * KK / 4 + 255) / 256, 256>>>(Wx, bx, Wh, bh);

    dim3 grid(NN / TN, BB / TM);
    lstm_fused<<<grid, 512, SMEM_TOTAL>>>(mA, mB, cx, w_ci, w_cf, w_co, out);
}